// round 14
// baseline (speedup 1.0000x reference)
#include <cuda_runtime.h>
#include <cstdint>

#define NB 8
#define NC 19
#define NH 512
#define NW 512
#define HW (NH * NW)            // 262144
#define NPIX (NB * HW)          // 2097152
#define NPAIR (HW / 2)          // 131072 pixel pairs
#define NITERS (NPAIR * NB)     // 1048576 flattened pair-iterations

// g_acc: [0..18] probs_sum_c, [19..37] inter_c, [38] focal [39] nll [40] slp [41] bnll
#define NACC 42

__device__ float g_acc[NACC];
__device__ int g_cnt[NC];
__device__ unsigned int g_ticket;
__device__ unsigned char g_diff[HW];

// ---------------------------------------------------------------------------
#define DB 128
#define DG ((HW / 4) / DB)      // 512 blocks

__global__ __launch_bounds__(DB) void diff_kernel(const int* __restrict__ tgt) {
    __shared__ unsigned int s_h[DB][NC];
#pragma unroll
    for (int c = 0; c < NC; c++) s_h[threadIdx.x][c] = 0u;

    const int idx = blockIdx.x * DB + threadIdx.x;      // over HW/4
    const int h = idx >> 7;
    const bool interior = (h >= 1) && (h <= NH - 2);
    const int4* t4 = (const int4*)tgt;

    uchar4 d = make_uchar4(0, 0, 0, 0);
#pragma unroll
    for (int b = 0; b < NB; b++) {
        int base = b * (HW / 4) + idx;
        int4 m = __ldg(t4 + base);
        s_h[threadIdx.x][m.x]++;
        s_h[threadIdx.x][m.y]++;
        s_h[threadIdx.x][m.z]++;
        s_h[threadIdx.x][m.w]++;
        if (interior) {
            int4 a = __ldg(t4 + base - NW / 4);
            int4 q = __ldg(t4 + base + NW / 4);
            d.x |= (unsigned char)((a.x != m.x) | (a.x != q.x));
            d.y |= (unsigned char)((a.y != m.y) | (a.y != q.y));
            d.z |= (unsigned char)((a.z != m.z) | (a.z != q.z));
            d.w |= (unsigned char)((a.w != m.w) | (a.w != q.w));
        }
    }
    ((uchar4*)g_diff)[idx] = d;

    __syncthreads();
    if (threadIdx.x < NC) {
        unsigned int s = 0;
#pragma unroll 8
        for (int r = 0; r < DB; r++) s += s_h[r][threadIdx.x];
        atomicAdd(&g_cnt[threadIdx.x], (int)s);
    }
}

// ---------------------------------------------------------------------------
__device__ __forceinline__ float warp_sum(float v) {
#pragma unroll
    for (int o = 16; o; o >>= 1) v += __shfl_down_sync(0xffffffffu, v, o);
    return v;
}

// ---------------------------------------------------------------------------
// Persistent single-wave grid; smem staging of raw logits; exp recomputed in
// pass 2 to keep register count under the 8-CTA/SM cap.
#define MBT 128
#define MAIN_BLOCKS 1184             // 8 CTAs/SM * 148 SMs, single wave
#define NTH (MAIN_BLOCKS * MBT)      // 151552 threads

__global__ __launch_bounds__(MBT, 8) void main_kernel(const float* __restrict__ in,
                                                      const int* __restrict__ tgt,
                                                      float* __restrict__ out) {
    __shared__ float2 s_x[NC][MBT];     // raw-logit staging (19.4 KB)
    __shared__ float s_int[4][NC];      // per-warp inter bins
    __shared__ float s_blk[NACC];
    __shared__ bool s_last;
    for (int t = threadIdx.x; t < NACC; t += MBT) s_blk[t] = 0.0f;
    for (int t = threadIdx.x; t < 4 * NC; t += MBT) ((float*)s_int)[t] = 0.0f;
    __syncthreads();

    const int tid = blockIdx.x * MBT + threadIdx.x;
    const int wid = threadIdx.x >> 5;
    const int lane = threadIdx.x & 31;

    const float2* in2 = (const float2*)in;
    const int2* tgt2 = (const int2*)tgt;

    float denom[NC];
#pragma unroll
    for (int c = 0; c < NC; c++) denom[c] = 0.0f;
    float a_focal = 0.0f, a_nll = 0.0f, a_slp = 0.0f, a_bnll = 0.0f;

#pragma unroll 1
    for (int idx = tid; idx < NITERS; idx += NTH) {
        const int pair = idx & (NPAIR - 1);
        const int b = idx >> 17;               // NPAIR == 2^17

        // boundary flags (g_diff is 256 KB, L2-resident)
        const int hw0 = 2 * pair;
        const int h = hw0 >> 9;
        const int w0 = hw0 & (NW - 1);
        float bm0 = 0.0f, bm1 = 0.0f;
        if (h >= 1 && h <= NH - 2) {
            unsigned char dm = g_diff[hw0];
            unsigned char dp = g_diff[hw0 + 1];
            if (w0 >= 1) bm0 = (float)(g_diff[hw0 - 1] | dm | dp);
            if (w0 + 1 <= NW - 2) bm1 = (float)(dm | dp | g_diff[hw0 + 2]);
        }

        const int2 tt = __ldg(tgt2 + b * (HW / 2) + pair);
        const int t0 = tt.x, t1 = tt.y;
        const float2* base = in2 + (size_t)b * (NC * (HW / 2)) + pair;

        // pass 1: load 19 float2, stage to smem, sum raw logits + partition fn
        float sA0 = 0.f, sB0 = 0.f, sA1 = 0.f, sB1 = 0.f;
        float zA0 = 0.f, zB0 = 0.f, zA1 = 0.f, zB1 = 0.f;
#pragma unroll
        for (int c = 0; c < NC; c++) {
            float2 v = __ldg(base + (size_t)c * (HW / 2));
            s_x[c][threadIdx.x] = v;
            float ex = __expf(v.x);
            float ey = __expf(v.y);
            if (c & 1) { sB0 += v.x; sB1 += v.y; zB0 += ex; zB1 += ey; }
            else       { sA0 += v.x; sA1 += v.y; zA0 += ex; zA1 += ey; }
        }
        const float sumx0 = sA0 + sB0, sumx1 = sA1 + sB1;
        const float Z0 = zA0 + zB0, Z1 = zA1 + zB1;

        // target logits from this thread's own staging slots (2 LDS)
        const float xt0 = s_x[t0][threadIdx.x].x;
        const float xt1 = s_x[t1][threadIdx.x].y;

        const float invZ0 = __fdividef(1.0f, Z0);
        const float invZ1 = __fdividef(1.0f, Z1);
        const float logZ0 = __logf(Z0);
        const float logZ1 = __logf(Z1);
        const float nll0 = logZ0 - xt0;
        const float nll1 = logZ1 - xt1;
        const float pt0 = __expf(xt0) * invZ0;
        const float pt1 = __expf(xt1) * invZ1;

        // pass 2: re-read staged logits, recompute exp, accumulate per-class
#pragma unroll
        for (int c = 0; c < NC; c++) {
            float2 v = s_x[c][threadIdx.x];
            denom[c] = fmaf(__expf(v.x), invZ0,
                       fmaf(__expf(v.y), invZ1, denom[c]));
        }

        const float om0 = 1.0f - pt0, om1 = 1.0f - pt1;
        a_focal = fmaf(om0 * om0, nll0, fmaf(om1 * om1, nll1, a_focal));
        a_nll += nll0 + nll1;
        a_slp += (sumx0 + sumx1) - (float)NC * (logZ0 + logZ1);
        a_bnll = fmaf(nll0, bm0, fmaf(nll1, bm1, a_bnll));

        atomicAdd(&s_int[wid][t0], pt0);
        atomicAdd(&s_int[wid][t1], pt1);
    }

    // --- block reduction (4 warps) ---
#pragma unroll
    for (int c = 0; c < NC; c++) {
        float v = warp_sum(denom[c]);
        if (lane == 0) atomicAdd(&s_blk[c], v);
    }
    {
        float v = warp_sum(a_focal);
        if (lane == 0) atomicAdd(&s_blk[38], v);
        v = warp_sum(a_nll);
        if (lane == 0) atomicAdd(&s_blk[39], v);
        v = warp_sum(a_slp);
        if (lane == 0) atomicAdd(&s_blk[40], v);
        v = warp_sum(a_bnll);
        if (lane == 0) atomicAdd(&s_blk[41], v);
    }
    __syncthreads();

    if (threadIdx.x < NC) {
        float vi = s_int[0][threadIdx.x] + s_int[1][threadIdx.x]
                 + s_int[2][threadIdx.x] + s_int[3][threadIdx.x];
        atomicAdd(&g_acc[NC + threadIdx.x], vi);
    }
    if (threadIdx.x < NACC && (threadIdx.x < NC || threadIdx.x >= 38)) {
        atomicAdd(&g_acc[threadIdx.x], s_blk[threadIdx.x]);
    }

    // --- ticketed finalize + state cleanup (graph-replay safe) ---
    __threadfence();
    __syncthreads();
    if (threadIdx.x == 0)
        s_last = (atomicAdd(&g_ticket, 1u) == MAIN_BLOCKS - 1);
    __syncthreads();

    if (s_last && threadIdx.x < 32) {
        const float Ninv = 1.0f / (float)NPIX;
        float ps = (lane < NC) ? g_acc[lane] : 0.0f;
        float it = (lane < NC) ? g_acc[NC + lane] : 0.0f;
        float cn = (lane < NC) ? (float)g_cnt[lane] : 0.0f;
        float d = 0.0f;
        if (lane < NC) d = 1.0f - (2.0f * it + 1e-5f) / (ps + cn + 1e-5f);
        d = warp_sum(d);
        if (lane == 0) {
            float dice = d / (float)NC;
            float focal = g_acc[38] * Ninv;
            float nll_sum = g_acc[39];
            float slp_sum = g_acc[40];
            float ce = (0.9f * nll_sum - 0.1f * slp_sum / (float)NC) * Ninv;
            float boundary = (nll_sum + 0.5f * g_acc[41]) * Ninv;
            out[0] = focal;
            out[1] = dice;
            out[2] = ce;
            out[3] = boundary;
            out[4] = focal + dice + ce + boundary;
        }
        if (lane < NACC) g_acc[lane] = 0.0f;
        if (lane + 32 < NACC) g_acc[lane + 32] = 0.0f;
        if (lane < NC) g_cnt[lane] = 0;
        if (lane == 0) g_ticket = 0u;
    }
}

// ---------------------------------------------------------------------------
extern "C" void kernel_launch(void* const* d_in, const int* in_sizes, int n_in,
                              void* d_out, int out_size) {
    const float* inputs = (const float*)d_in[0];
    const int* targets = (const int*)d_in[1];
    float* out = (float*)d_out;

    diff_kernel<<<DG, DB>>>(targets);
    main_kernel<<<MAIN_BLOCKS, MBT>>>(inputs, targets, out);
}

// round 15
// speedup vs baseline: 1.0207x; 1.0207x over previous
#include <cuda_runtime.h>
#include <cstdint>

#define NB 8
#define NC 19
#define NH 512
#define NW 512
#define HW (NH * NW)            // 262144
#define NPIX (NB * HW)          // 2097152
#define NPAIR (HW / 2)          // 131072 pixel pairs
#define NITERS (NPAIR * NB)     // 1048576 flattened pair-iterations

// g_acc: [0..18] probs_sum_c, [19..37] inter_c, [38] focal [39] nll [40] slp [41] bnll
#define NACC 42

__device__ float g_acc[NACC];
__device__ int g_cnt[NC];
__device__ unsigned int g_ticket;
__device__ unsigned char g_diff[HW];

// ---------------------------------------------------------------------------
#define DB 128
#define DG ((HW / 4) / DB)      // 512 blocks

__global__ __launch_bounds__(DB) void diff_kernel(const int* __restrict__ tgt) {
    __shared__ unsigned int s_h[DB][NC];
#pragma unroll
    for (int c = 0; c < NC; c++) s_h[threadIdx.x][c] = 0u;

    const int idx = blockIdx.x * DB + threadIdx.x;      // over HW/4
    const int h = idx >> 7;
    const bool interior = (h >= 1) && (h <= NH - 2);
    const int4* t4 = (const int4*)tgt;

    uchar4 d = make_uchar4(0, 0, 0, 0);
#pragma unroll
    for (int b = 0; b < NB; b++) {
        int base = b * (HW / 4) + idx;
        int4 m = __ldg(t4 + base);
        s_h[threadIdx.x][m.x]++;
        s_h[threadIdx.x][m.y]++;
        s_h[threadIdx.x][m.z]++;
        s_h[threadIdx.x][m.w]++;
        if (interior) {
            int4 a = __ldg(t4 + base - NW / 4);
            int4 q = __ldg(t4 + base + NW / 4);
            d.x |= (unsigned char)((a.x != m.x) | (a.x != q.x));
            d.y |= (unsigned char)((a.y != m.y) | (a.y != q.y));
            d.z |= (unsigned char)((a.z != m.z) | (a.z != q.z));
            d.w |= (unsigned char)((a.w != m.w) | (a.w != q.w));
        }
    }
    ((uchar4*)g_diff)[idx] = d;

    __syncthreads();
    if (threadIdx.x < NC) {
        unsigned int s = 0;
#pragma unroll 8
        for (int r = 0; r < DB; r++) s += s_h[r][threadIdx.x];
        atomicAdd(&g_cnt[threadIdx.x], (int)s);
    }
}

// ---------------------------------------------------------------------------
__device__ __forceinline__ float warp_sum(float v) {
#pragma unroll
    for (int o = 16; o; o >>= 1) v += __shfl_down_sync(0xffffffffu, v, o);
    return v;
}

// ---------------------------------------------------------------------------
// Packed f32x2 helpers (PTX-only on sm_103a; ptxas won't emit FFMA2 from C++).
union F2 {
    float2 f;
    unsigned long long u;
};

#define ADD2(d, a, b) \
    asm("add.rn.f32x2 %0, %1, %2;" : "=l"((d).u) : "l"((a).u), "l"((b).u))
#define MUL2(d, a, b) \
    asm("mul.rn.f32x2 %0, %1, %2;" : "=l"((d).u) : "l"((a).u), "l"((b).u))
#define FMA2(d, a, b, c) \
    asm("fma.rn.f32x2 %0, %1, %2, %3;" : "=l"((d).u) : "l"((a).u), "l"((b).u), "l"((c).u))
#define EX2F(d, s) \
    asm("ex2.approx.f32 %0, %1;" : "=f"(d) : "f"(s))

// ---------------------------------------------------------------------------
// Persistent single-wave grid; smem-staged target select; packed f32x2 math.
#define MBT 128
#define MAIN_BLOCKS 740              // 5 CTAs/SM * 148 SMs, single wave
#define NTH (MAIN_BLOCKS * MBT)      // 94720 threads

__global__ __launch_bounds__(MBT, 5) void main_kernel(const float* __restrict__ in,
                                                      const int* __restrict__ tgt,
                                                      float* __restrict__ out) {
    __shared__ float2 s_x[NC][MBT];     // raw-logit staging (19.4 KB)
    __shared__ float s_int[4][NC];      // per-warp inter bins
    __shared__ float s_blk[NACC];
    __shared__ bool s_last;
    for (int t = threadIdx.x; t < NACC; t += MBT) s_blk[t] = 0.0f;
    for (int t = threadIdx.x; t < 4 * NC; t += MBT) ((float*)s_int)[t] = 0.0f;
    __syncthreads();

    const int tid = blockIdx.x * MBT + threadIdx.x;
    const int wid = threadIdx.x >> 5;
    const int lane = threadIdx.x & 31;

    const float2* in2 = (const float2*)in;
    const int2* tgt2 = (const int2*)tgt;

    F2 LOG2E;
    LOG2E.f.x = 1.4426950408889634f;
    LOG2E.f.y = 1.4426950408889634f;

    F2 denom2[NC];
#pragma unroll
    for (int c = 0; c < NC; c++) denom2[c].u = 0ull;     // (0.0f, 0.0f)

    F2 sx2; sx2.u = 0ull;               // running packed sum of raw logits
    float a_logz = 0.0f;                // running sum of logZ (both pixels)
    float a_focal = 0.0f, a_nll = 0.0f, a_bnll = 0.0f;

#pragma unroll 1
    for (int idx = tid; idx < NITERS; idx += NTH) {
        const int pair = idx & (NPAIR - 1);
        const int b = idx >> 17;               // NPAIR == 2^17

        // boundary flags (g_diff is 256 KB, L2-resident)
        const int hw0 = 2 * pair;
        const int h = hw0 >> 9;
        const int w0 = hw0 & (NW - 1);
        float bm0 = 0.0f, bm1 = 0.0f;
        if (h >= 1 && h <= NH - 2) {
            unsigned char dm = g_diff[hw0];
            unsigned char dp = g_diff[hw0 + 1];
            if (w0 >= 1) bm0 = (float)(g_diff[hw0 - 1] | dm | dp);
            if (w0 + 1 <= NW - 2) bm1 = (float)(dm | dp | g_diff[hw0 + 2]);
        }

        const int2 tt = __ldg(tgt2 + b * (HW / 2) + pair);
        const int t0 = tt.x, t1 = tt.y;
        const float2* base = in2 + (size_t)b * (NC * (HW / 2)) + pair;

        // pass 1: load, stage, packed sums + exponentials (kept in reg pairs)
        F2 e2[NC];
        F2 z2; z2.u = 0ull;
#pragma unroll
        for (int c = 0; c < NC; c++) {
            F2 v;
            v.f = __ldg(base + (size_t)c * (HW / 2));
            s_x[c][threadIdx.x] = v.f;
            ADD2(sx2, sx2, v);                 // global raw-logit sum
            F2 y;
            MUL2(y, v, LOG2E);                 // x * log2(e), packed
            EX2F(e2[c].f.x, y.f.x);            // MUFU reads the pair halves
            EX2F(e2[c].f.y, y.f.y);
            ADD2(z2, z2, e2[c]);               // partition functions, packed
        }
        const float Z0 = z2.f.x, Z1 = z2.f.y;

        // target logits from this thread's own staging slots (2 LDS)
        const float xt0 = s_x[t0][threadIdx.x].x;
        const float xt1 = s_x[t1][threadIdx.x].y;

        const float invZ0 = __fdividef(1.0f, Z0);
        const float invZ1 = __fdividef(1.0f, Z1);
        const float logZ0 = __logf(Z0);
        const float logZ1 = __logf(Z1);
        const float nll0 = logZ0 - xt0;
        const float nll1 = logZ1 - xt1;
        const float pt0 = __expf(xt0) * invZ0;
        const float pt1 = __expf(xt1) * invZ1;

        // pass 2: packed per-class probability accumulation
        F2 i2;
        i2.f.x = invZ0;
        i2.f.y = invZ1;
#pragma unroll
        for (int c = 0; c < NC; c++) {
            FMA2(denom2[c], e2[c], i2, denom2[c]);
        }

        const float om0 = 1.0f - pt0, om1 = 1.0f - pt1;
        a_focal = fmaf(om0 * om0, nll0, fmaf(om1 * om1, nll1, a_focal));
        a_nll += nll0 + nll1;
        a_logz += logZ0 + logZ1;
        a_bnll = fmaf(nll0, bm0, fmaf(nll1, bm1, a_bnll));

        atomicAdd(&s_int[wid][t0], pt0);
        atomicAdd(&s_int[wid][t1], pt1);
    }

    // a_slp = sum of per-pixel (sum_c x_c - NC*logZ), accumulated separately
    const float a_slp = (sx2.f.x + sx2.f.y) - (float)NC * a_logz;

    // --- block reduction (4 warps) ---
#pragma unroll
    for (int c = 0; c < NC; c++) {
        float v = warp_sum(denom2[c].f.x + denom2[c].f.y);
        if (lane == 0) atomicAdd(&s_blk[c], v);
    }
    {
        float v = warp_sum(a_focal);
        if (lane == 0) atomicAdd(&s_blk[38], v);
        v = warp_sum(a_nll);
        if (lane == 0) atomicAdd(&s_blk[39], v);
        v = warp_sum(a_slp);
        if (lane == 0) atomicAdd(&s_blk[40], v);
        v = warp_sum(a_bnll);
        if (lane == 0) atomicAdd(&s_blk[41], v);
    }
    __syncthreads();

    if (threadIdx.x < NC) {
        float vi = s_int[0][threadIdx.x] + s_int[1][threadIdx.x]
                 + s_int[2][threadIdx.x] + s_int[3][threadIdx.x];
        atomicAdd(&g_acc[NC + threadIdx.x], vi);
    }
    if (threadIdx.x < NACC && (threadIdx.x < NC || threadIdx.x >= 38)) {
        atomicAdd(&g_acc[threadIdx.x], s_blk[threadIdx.x]);
    }

    // --- ticketed finalize + state cleanup (graph-replay safe) ---
    __threadfence();
    __syncthreads();
    if (threadIdx.x == 0)
        s_last = (atomicAdd(&g_ticket, 1u) == MAIN_BLOCKS - 1);
    __syncthreads();

    if (s_last && threadIdx.x < 32) {
        const float Ninv = 1.0f / (float)NPIX;
        float ps = (lane < NC) ? g_acc[lane] : 0.0f;
        float it = (lane < NC) ? g_acc[NC + lane] : 0.0f;
        float cn = (lane < NC) ? (float)g_cnt[lane] : 0.0f;
        float d = 0.0f;
        if (lane < NC) d = 1.0f - (2.0f * it + 1e-5f) / (ps + cn + 1e-5f);
        d = warp_sum(d);
        if (lane == 0) {
            float dice = d / (float)NC;
            float focal = g_acc[38] * Ninv;
            float nll_sum = g_acc[39];
            float slp_sum = g_acc[40];
            float ce = (0.9f * nll_sum - 0.1f * slp_sum / (float)NC) * Ninv;
            float boundary = (nll_sum + 0.5f * g_acc[41]) * Ninv;
            out[0] = focal;
            out[1] = dice;
            out[2] = ce;
            out[3] = boundary;
            out[4] = focal + dice + ce + boundary;
        }
        if (lane < NACC) g_acc[lane] = 0.0f;
        if (lane + 32 < NACC) g_acc[lane + 32] = 0.0f;
        if (lane < NC) g_cnt[lane] = 0;
        if (lane == 0) g_ticket = 0u;
    }
}

// ---------------------------------------------------------------------------
extern "C" void kernel_launch(void* const* d_in, const int* in_sizes, int n_in,
                              void* d_out, int out_size) {
    const float* inputs = (const float*)d_in[0];
    const int* targets = (const int*)d_in[1];
    float* out = (float*)d_out;

    diff_kernel<<<DG, DB>>>(targets);
    main_kernel<<<MAIN_BLOCKS, MBT>>>(inputs, targets, out);
}

// round 16
// speedup vs baseline: 1.0823x; 1.0603x over previous
#include <cuda_runtime.h>
#include <cstdint>

#define NB 8
#define NC 19
#define NH 512
#define NW 512
#define HW (NH * NW)            // 262144
#define NPIX (NB * HW)          // 2097152
#define NPAIR (HW / 2)          // 131072 pixel pairs
#define NITERS (NPAIR * NB)     // 1048576 flattened pair-iterations

// g_acc: [0..18] probs_sum_c, [19..37] inter_c, [38] focal [39] nll [40] slp [41] bnll
#define NACC 42

__device__ float g_acc[NACC];
__device__ int g_cnt[NC];
__device__ unsigned int g_ticket;
__device__ unsigned char g_bm[HW];      // per-pixel boundary flag (0/1)

// ---------------------------------------------------------------------------
// One block per image row: 128 threads x int4 = 512 columns. Computes column
// diffs, ORs horizontally in smem, emits packed per-pixel boundary bytes and
// the target histogram.
#define DB 128

__global__ __launch_bounds__(DB) void diff_kernel(const int* __restrict__ tgt) {
    __shared__ uchar4 s_d[DB];          // per-column diff flags for this row
    __shared__ unsigned int s_h[DB][NC];
#pragma unroll
    for (int c = 0; c < NC; c++) s_h[threadIdx.x][c] = 0u;

    const int h = blockIdx.x;                    // row
    const int idx = h * DB + threadIdx.x;        // int4 index into [512][128]
    const bool interior_h = (h >= 1) && (h <= NH - 2);
    const int4* t4 = (const int4*)tgt;

    uchar4 d = make_uchar4(0, 0, 0, 0);
#pragma unroll
    for (int b = 0; b < NB; b++) {
        int base = b * (HW / 4) + idx;
        int4 m = __ldg(t4 + base);
        s_h[threadIdx.x][m.x]++;
        s_h[threadIdx.x][m.y]++;
        s_h[threadIdx.x][m.z]++;
        s_h[threadIdx.x][m.w]++;
        if (interior_h) {
            int4 a = __ldg(t4 + base - NW / 4);
            int4 q = __ldg(t4 + base + NW / 4);
            d.x |= (unsigned char)((a.x != m.x) | (a.x != q.x));
            d.y |= (unsigned char)((a.y != m.y) | (a.y != q.y));
            d.z |= (unsigned char)((a.z != m.z) | (a.z != q.z));
            d.w |= (unsigned char)((a.w != m.w) | (a.w != q.w));
        }
    }
    s_d[threadIdx.x] = d;
    __syncthreads();

    // horizontal 3-way OR -> per-pixel boundary bytes (interior only)
    unsigned char left = (threadIdx.x == 0) ? 0 : s_d[threadIdx.x - 1].w;
    unsigned char right = (threadIdx.x == DB - 1) ? 0 : s_d[threadIdx.x + 1].x;
    uchar4 bm = make_uchar4(0, 0, 0, 0);
    if (interior_h) {
        bm.x = (unsigned char)(left | d.x | d.y);
        bm.y = (unsigned char)(d.x | d.y | d.z);
        bm.z = (unsigned char)(d.y | d.z | d.w);
        bm.w = (unsigned char)(d.z | d.w | right);
        const int w0 = 4 * threadIdx.x;
        if (w0 == 0) bm.x = 0;                   // w == 0 edge
        if (w0 + 3 == NW - 1) bm.w = 0;          // w == 511 edge
    }
    ((uchar4*)g_bm)[idx] = bm;

    __syncthreads();
    if (threadIdx.x < NC) {
        unsigned int s = 0;
#pragma unroll 8
        for (int r = 0; r < DB; r++) s += s_h[r][threadIdx.x];
        atomicAdd(&g_cnt[threadIdx.x], (int)s);
    }
}

// ---------------------------------------------------------------------------
__device__ __forceinline__ float warp_sum(float v) {
#pragma unroll
    for (int o = 16; o; o >>= 1) v += __shfl_down_sync(0xffffffffu, v, o);
    return v;
}

// ---------------------------------------------------------------------------
// Persistent single-wave grid (R12 body); precomputed boundary bytes.
#define MBT 128
#define MAIN_BLOCKS 740              // 5 CTAs/SM * 148 SMs, single wave
#define NTH (MAIN_BLOCKS * MBT)      // 94720 threads

__global__ __launch_bounds__(MBT, 5) void main_kernel(const float* __restrict__ in,
                                                      const int* __restrict__ tgt,
                                                      float* __restrict__ out) {
    __shared__ float2 s_x[NC][MBT];     // raw-logit staging (19.4 KB)
    __shared__ float s_int[4][NC];      // per-warp inter bins
    __shared__ float s_blk[NACC];
    __shared__ bool s_last;
    for (int t = threadIdx.x; t < NACC; t += MBT) s_blk[t] = 0.0f;
    for (int t = threadIdx.x; t < 4 * NC; t += MBT) ((float*)s_int)[t] = 0.0f;
    __syncthreads();

    const int tid = blockIdx.x * MBT + threadIdx.x;
    const int wid = threadIdx.x >> 5;
    const int lane = threadIdx.x & 31;

    const float2* in2 = (const float2*)in;
    const int2* tgt2 = (const int2*)tgt;
    const uchar2* bm2 = (const uchar2*)g_bm;

    float denom[NC];
#pragma unroll
    for (int c = 0; c < NC; c++) denom[c] = 0.0f;
    float a_focal = 0.0f, a_nll = 0.0f, a_slp = 0.0f, a_bnll = 0.0f;

#pragma unroll 1
    for (int idx = tid; idx < NITERS; idx += NTH) {
        const int pair = idx & (NPAIR - 1);
        const int b = idx >> 17;               // NPAIR == 2^17

        // boundary flags: one L2-resident 2-byte load
        const uchar2 gb = __ldg(bm2 + pair);
        const float bm0 = (float)gb.x;
        const float bm1 = (float)gb.y;

        const int2 tt = __ldg(tgt2 + b * (HW / 2) + pair);
        const int t0 = tt.x, t1 = tt.y;
        const float2* base = in2 + (size_t)b * (NC * (HW / 2)) + pair;

        // load 19 float2; stage raw logits to smem; exps stay in registers
        float2 e[NC];
        float sA0 = 0.f, sB0 = 0.f, sA1 = 0.f, sB1 = 0.f;
        float zA0 = 0.f, zB0 = 0.f, zA1 = 0.f, zB1 = 0.f;
#pragma unroll
        for (int c = 0; c < NC; c++) {
            float2 v = __ldg(base + (size_t)c * (HW / 2));
            s_x[c][threadIdx.x] = v;
            float ex = __expf(v.x);
            float ey = __expf(v.y);
            if (c & 1) { sB0 += v.x; sB1 += v.y; zB0 += ex; zB1 += ey; }
            else       { sA0 += v.x; sA1 += v.y; zA0 += ex; zA1 += ey; }
            e[c].x = ex; e[c].y = ey;
        }
        const float sumx0 = sA0 + sB0, sumx1 = sA1 + sB1;
        const float Z0 = zA0 + zB0, Z1 = zA1 + zB1;

        // target logits: 2 indexed LDS from this thread's own staging slots
        const float xt0 = s_x[t0][threadIdx.x].x;
        const float xt1 = s_x[t1][threadIdx.x].y;

        const float invZ0 = __fdividef(1.0f, Z0);
        const float invZ1 = __fdividef(1.0f, Z1);
        const float logZ0 = __logf(Z0);
        const float logZ1 = __logf(Z1);
        const float nll0 = logZ0 - xt0;
        const float nll1 = logZ1 - xt1;
        const float pt0 = __expf(xt0) * invZ0;
        const float pt1 = __expf(xt1) * invZ1;

#pragma unroll
        for (int c = 0; c < NC; c++) {
            denom[c] = fmaf(e[c].x, invZ0, fmaf(e[c].y, invZ1, denom[c]));
        }

        const float om0 = 1.0f - pt0, om1 = 1.0f - pt1;
        a_focal = fmaf(om0 * om0, nll0, fmaf(om1 * om1, nll1, a_focal));
        a_nll += nll0 + nll1;
        a_slp += (sumx0 + sumx1) - (float)NC * (logZ0 + logZ1);
        a_bnll = fmaf(nll0, bm0, fmaf(nll1, bm1, a_bnll));

        atomicAdd(&s_int[wid][t0], pt0);
        atomicAdd(&s_int[wid][t1], pt1);
    }

    // --- block reduction (4 warps) ---
#pragma unroll
    for (int c = 0; c < NC; c++) {
        float v = warp_sum(denom[c]);
        if (lane == 0) atomicAdd(&s_blk[c], v);
    }
    {
        float v = warp_sum(a_focal);
        if (lane == 0) atomicAdd(&s_blk[38], v);
        v = warp_sum(a_nll);
        if (lane == 0) atomicAdd(&s_blk[39], v);
        v = warp_sum(a_slp);
        if (lane == 0) atomicAdd(&s_blk[40], v);
        v = warp_sum(a_bnll);
        if (lane == 0) atomicAdd(&s_blk[41], v);
    }
    __syncthreads();

    if (threadIdx.x < NC) {
        float vi = s_int[0][threadIdx.x] + s_int[1][threadIdx.x]
                 + s_int[2][threadIdx.x] + s_int[3][threadIdx.x];
        atomicAdd(&g_acc[NC + threadIdx.x], vi);
    }
    if (threadIdx.x < NACC && (threadIdx.x < NC || threadIdx.x >= 38)) {
        atomicAdd(&g_acc[threadIdx.x], s_blk[threadIdx.x]);
    }

    // --- ticketed finalize + state cleanup (graph-replay safe) ---
    __threadfence();
    __syncthreads();
    if (threadIdx.x == 0)
        s_last = (atomicAdd(&g_ticket, 1u) == MAIN_BLOCKS - 1);
    __syncthreads();

    if (s_last && threadIdx.x < 32) {
        const float Ninv = 1.0f / (float)NPIX;
        float ps = (lane < NC) ? g_acc[lane] : 0.0f;
        float it = (lane < NC) ? g_acc[NC + lane] : 0.0f;
        float cn = (lane < NC) ? (float)g_cnt[lane] : 0.0f;
        float d = 0.0f;
        if (lane < NC) d = 1.0f - (2.0f * it + 1e-5f) / (ps + cn + 1e-5f);
        d = warp_sum(d);
        if (lane == 0) {
            float dice = d / (float)NC;
            float focal = g_acc[38] * Ninv;
            float nll_sum = g_acc[39];
            float slp_sum = g_acc[40];
            float ce = (0.9f * nll_sum - 0.1f * slp_sum / (float)NC) * Ninv;
            float boundary = (nll_sum + 0.5f * g_acc[41]) * Ninv;
            out[0] = focal;
            out[1] = dice;
            out[2] = ce;
            out[3] = boundary;
            out[4] = focal + dice + ce + boundary;
        }
        if (lane < NACC) g_acc[lane] = 0.0f;
        if (lane + 32 < NACC) g_acc[lane + 32] = 0.0f;
        if (lane < NC) g_cnt[lane] = 0;
        if (lane == 0) g_ticket = 0u;
    }
}

// ---------------------------------------------------------------------------
extern "C" void kernel_launch(void* const* d_in, const int* in_sizes, int n_in,
                              void* d_out, int out_size) {
    const float* inputs = (const float*)d_in[0];
    const int* targets = (const int*)d_in[1];
    float* out = (float*)d_out;

    diff_kernel<<<NH, DB>>>(targets);
    main_kernel<<<MAIN_BLOCKS, MBT>>>(inputs, targets, out);
}